// round 7
// baseline (speedup 1.0000x reference)
#include <cuda_runtime.h>

// QuantumConv closed form (R1 derivation):
//   p1 = 0.5 - 0.5*cos(pi*t0)*cos(pi*t1)*cos(f0)
//            + 0.5*sin(pi*t0)*cos(pi*t1)*sin(f0)*cos(f1)*cos(f8)
// with f0 = in[b,y,x], f1 = in[b,y,x+1], f8 = in[b,y+2,x+2].
//
// R7: geometry-matched launch — block(32,13), grid(2,16) — so (x, y, b) come
// straight from special registers: zero integer divisions on the address
// critical path, and blocks drop 85 -> 32 (shorter dispatch/drain tail).
// Keeps R5's max-TLP 1-output/thread shape and FMA-folded epilogue.

#define HH 28
#define WW 28
#define NOUT 26

__global__ __launch_bounds__(416, 1)
void qconv_closed_form(const float* __restrict__ in,
                       const float* __restrict__ theta,
                       float* __restrict__ out) {
    int x = threadIdx.x;                          // 0..31, active if <26
    int y = blockIdx.x * 13 + threadIdx.y;        // 0..25
    int b = blockIdx.y;                           // 0..15
    if (x >= NOUT) return;

    const float* base = in + (b * HH + y) * WW + x;

    // Batch all 5 loads before any dependent math (MLP=5, L2-warm on replay).
    float f0 = __ldg(base);
    float f1 = __ldg(base + 1);
    float f8 = __ldg(base + 2 * WW + 2);
    float t0 = __ldg(theta);
    float t1 = __ldg(theta + 1);

    const float PI = 3.14159265358979323846f;

    // Theta MUFUs — independent of the data MUFUs below, overlap freely.
    float sa, ca;
    __sincosf(PI * t0, &sa, &ca);
    float cbh = 0.5f * __cosf(PI * t1);
    float K1h = ca * cbh;        // 0.5 * cos(pi t0) cos(pi t1)
    float K2h = sa * cbh;        // 0.5 * sin(pi t0) cos(pi t1)

    float s0, c0;
    __sincosf(f0, &s0, &c0);
    float c18 = __cosf(f1) * __cosf(f8);

    out[(b * NOUT + y) * NOUT + x] = fmaf(K2h, s0 * c18, fmaf(-K1h, c0, 0.5f));
}

extern "C" void kernel_launch(void* const* d_in, const int* in_sizes, int n_in,
                              void* d_out, int out_size) {
    const float* input = (const float*)d_in[0];   // (16,28,28) float32
    const float* theta = (const float*)d_in[1];   // (1,27) float32
    float* out = (float*)d_out;                   // (16,26,26) float32

    (void)in_sizes; (void)n_in; (void)out_size;

    dim3 block(32, 13);                           // 416 threads
    dim3 grid(2, 16);                             // 32 blocks, single wave
    qconv_closed_form<<<grid, block>>>(input, theta, out);
}

// round 8
// speedup vs baseline: 1.6649x; 1.6649x over previous
#include <cuda_runtime.h>

// QuantumConv closed form (R1 derivation):
//   p1 = 0.5 - 0.5*cos(pi*t0)*cos(pi*t1)*cos(f0)
//            + 0.5*sin(pi*t0)*cos(pi*t1)*sin(f0)*cos(f1)*cos(f8)
// with f0 = in[b,y,x], f1 = in[b,y,x+1], f8 = in[b,y+2,x+2].
//
// R8 (final): exact revert to the R5 configuration — the only shape that hits
// the 4.608us harness floor (reproduced twice). Session findings:
//   - R4: ILP-4/float4 regressed (latency-bound; TLP > ILP here)
//   - R7: 416-thread blocks regressed replay time 2x despite best ncu dur
//   - 85 x 128 1D, 1 output/thread, MUFU trig, FMA epilogue = floor.

#define BATCH 16
#define HH 28
#define WW 28
#define NOUT 26
#define NP (BATCH * NOUT * NOUT)   // 10816

__global__ __launch_bounds__(128, 1)
void qconv_closed_form(const float* __restrict__ in,
                       const float* __restrict__ theta,
                       float* __restrict__ out) {
    int idx = blockIdx.x * blockDim.x + threadIdx.x;
    if (idx >= NP) return;

    int t = idx / NOUT;          // const-div -> mulhi
    int x = idx - t * NOUT;
    int b = t / NOUT;
    int y = t - b * NOUT;

    const float* base = in + (b * HH + y) * WW + x;

    // Batch all 5 loads before any dependent math (MLP=5, L2-warm on replay).
    float f0 = __ldg(base);
    float f1 = __ldg(base + 1);
    float f8 = __ldg(base + 2 * WW + 2);
    float t0 = __ldg(theta);
    float t1 = __ldg(theta + 1);

    const float PI = 3.14159265358979323846f;

    // Theta MUFUs — independent of the data MUFUs below, overlap freely.
    float sa, ca;
    __sincosf(PI * t0, &sa, &ca);
    float cbh = 0.5f * __cosf(PI * t1);
    float K1h = ca * cbh;        // 0.5 * cos(pi t0) cos(pi t1)
    float K2h = sa * cbh;        // 0.5 * sin(pi t0) cos(pi t1)

    float s0, c0;
    __sincosf(f0, &s0, &c0);
    float c18 = __cosf(f1) * __cosf(f8);

    out[idx] = fmaf(K2h, s0 * c18, fmaf(-K1h, c0, 0.5f));
}

extern "C" void kernel_launch(void* const* d_in, const int* in_sizes, int n_in,
                              void* d_out, int out_size) {
    const float* input = (const float*)d_in[0];   // (16,28,28) float32
    const float* theta = (const float*)d_in[1];   // (1,27) float32
    float* out = (float*)d_out;                   // (16,26,26) float32

    (void)in_sizes; (void)n_in; (void)out_size;

    int threads = 128;
    int blocks = (NP + threads - 1) / threads;    // 85 blocks, single wave
    qconv_closed_form<<<blocks, threads>>>(input, theta, out);
}